// round 15
// baseline (speedup 1.0000x reference)
#include <cuda_runtime.h>
#include <math.h>

// ---------------- problem constants ----------------
#define DMc   256
#define Lc    4096
#define DSc   128
#define DIc   512
#define NHc   8
#define HDc   64
#define CDc   768
#define DIPc  1288
#define CSc   256
#define NCc   16
#define EPSc  1e-5f
#define LDT   136

// ---------------- device scratch ----------------
__device__ float g_U  [4 * Lc * DMc];
__device__ float g_Z  [4 * Lc * DIPc];
__device__ float g_xBC[4 * Lc * CDc];
__device__ float g_dt [4 * Lc * NHc];
__device__ float g_dA [4 * Lc * NHc];
__device__ float g_CB [4 * NCc * CSc * CSc];
__device__ float g_y  [4 * Lc * DIc];          // gated (y_total * silu(z)), pre-norm
__device__ float g_ssp[4 * Lc * 16];           // partial sum-squares: per (row) 8 heads x 2 halves
__device__ float g_st [4 * NCc * NHc * HDc * DSc];
__device__ float g_pv [4 * NCc * NHc * HDc * DSc];
__device__ float g_cat[Lc * 4 * DMc];

__device__ __forceinline__ float silu_f(float x) { return x / (1.f + __expf(-x)); }

// ---------------- tf32 helpers ----------------
__device__ __forceinline__ unsigned f2t(float x) {
    unsigned r; asm("cvt.rna.tf32.f32 %0, %1;" : "=r"(r) : "f"(x)); return r;
}
__device__ __forceinline__ float f2tf(float x) { return __uint_as_float(f2t(x)); }

__device__ __forceinline__ void mma_tf32(float& d0, float& d1, float& d2, float& d3,
                                         unsigned a0, unsigned a1, unsigned a2, unsigned a3,
                                         unsigned b0, unsigned b1) {
    asm volatile("mma.sync.aligned.m16n8k8.row.col.f32.tf32.tf32.f32 "
                 "{%0,%1,%2,%3}, {%4,%5,%6,%7}, {%8,%9}, {%0,%1,%2,%3};\n"
                 : "+f"(d0), "+f"(d1), "+f"(d2), "+f"(d3)
                 : "r"(a0), "r"(a1), "r"(a2), "r"(a3), "r"(b0), "r"(b1));
}

template<int MF, int NF>
__device__ __forceinline__ void mma_tile(const float (*As)[LDT], const float (*Bs)[LDT],
                                         float acc[MF][NF][4], int wm0, int wn0, int lane) {
    int gid = lane >> 2, t4 = lane & 3;
    #pragma unroll
    for (int ks = 0; ks < 16; ks += 8) {
        unsigned a[MF][4], b[NF][2];
        #pragma unroll
        for (int mi = 0; mi < MF; mi++) {
            int m = wm0 + mi * 16 + gid;
            a[mi][0] = __float_as_uint(As[ks + t4    ][m]);
            a[mi][1] = __float_as_uint(As[ks + t4    ][m + 8]);
            a[mi][2] = __float_as_uint(As[ks + t4 + 4][m]);
            a[mi][3] = __float_as_uint(As[ks + t4 + 4][m + 8]);
        }
        #pragma unroll
        for (int nj = 0; nj < NF; nj++) {
            int n = wn0 + nj * 8 + gid;
            b[nj][0] = __float_as_uint(Bs[ks + t4    ][n]);
            b[nj][1] = __float_as_uint(Bs[ks + t4 + 4][n]);
        }
        #pragma unroll
        for (int mi = 0; mi < MF; mi++)
            #pragma unroll
            for (int nj = 0; nj < NF; nj++)
                mma_tf32(acc[mi][nj][0], acc[mi][nj][1], acc[mi][nj][2], acc[mi][nj][3],
                         a[mi][0], a[mi][1], a[mi][2], a[mi][3], b[nj][0], b[nj][1]);
    }
}

// ======== register-staged fetch / smem store (BK=16) ========
__device__ __forceinline__ void fetch128(const float* __restrict__ G, int ld, int k0,
                                         float4 r[2], int tid) {
    #pragma unroll
    for (int h = 0; h < 2; h++) {
        int e = tid * 4 + h * 1024; int kk = e & 15; int rr = e >> 4;
        r[h] = *(const float4*)(G + (size_t)rr * ld + k0 + kk);
    }
}
__device__ __forceinline__ void fetch128m(const float* __restrict__ G, int ld, int k0, int rlim,
                                          float4 r[2], int tid) {
    #pragma unroll
    for (int h = 0; h < 2; h++) {
        int e = tid * 4 + h * 1024; int kk = e & 15; int rr = e >> 4;
        r[h] = make_float4(0.f, 0.f, 0.f, 0.f);
        if (rr < rlim) r[h] = *(const float4*)(G + (size_t)rr * ld + k0 + kk);
    }
}
__device__ __forceinline__ void store128(const float4 r[2], float (*S)[LDT], int tid) {
    #pragma unroll
    for (int h = 0; h < 2; h++) {
        int e = tid * 4 + h * 1024; int kk = e & 15; int rr = e >> 4;
        S[kk][rr] = f2tf(r[h].x); S[kk+1][rr] = f2tf(r[h].y);
        S[kk+2][rr] = f2tf(r[h].z); S[kk+3][rr] = f2tf(r[h].w);
    }
}
__device__ __forceinline__ void store128s(const float4 r[2], float (*S)[LDT], int tid) {
    #pragma unroll
    for (int h = 0; h < 2; h++) {
        int e = tid * 4 + h * 1024; int kk = e & 15; int rr = e >> 4;
        S[kk][rr] = f2tf(silu_f(r[h].x)); S[kk+1][rr] = f2tf(silu_f(r[h].y));
        S[kk+2][rr] = f2tf(silu_f(r[h].z)); S[kk+3][rr] = f2tf(silu_f(r[h].w));
    }
}
// normalized store: v * rowScale[rr] * norm_w[k]
__device__ __forceinline__ void store128n(const float4 r[2], float (*S)[LDT], int tid,
                                          const float* rs, const float* nw, int k0) {
    #pragma unroll
    for (int h = 0; h < 2; h++) {
        int e = tid * 4 + h * 1024; int kk = e & 15; int rr = e >> 4;
        float sc = rs[rr];
        S[kk][rr]   = f2tf(r[h].x * sc * nw[k0 + kk]);
        S[kk+1][rr] = f2tf(r[h].y * sc * nw[k0 + kk + 1]);
        S[kk+2][rr] = f2tf(r[h].z * sc * nw[k0 + kk + 2]);
        S[kk+3][rr] = f2tf(r[h].w * sc * nw[k0 + kk + 3]);
    }
}
__device__ __forceinline__ void fetch64(const float* __restrict__ G, int ld, int k0,
                                        float4& r, int tid) {
    int e = tid * 4; int kk = e & 15; int rr = e >> 4;
    r = *(const float4*)(G + (size_t)rr * ld + k0 + kk);
}
__device__ __forceinline__ void store64(const float4 r, float (*S)[LDT], int tid) {
    int e = tid * 4; int kk = e & 15; int rr = e >> 4;
    S[kk][rr] = f2tf(r.x); S[kk+1][rr] = f2tf(r.y);
    S[kk+2][rr] = f2tf(r.z); S[kk+3][rr] = f2tf(r.w);
}

// ---------------- 0. gather + transpose ----------------
__global__ void k_buildU(const float* __restrict__ pts) {
    int d  = blockIdx.z;
    int lt = blockIdx.x * 32;
    int mt = blockIdx.y * 32;
    __shared__ float tile[32][33];
    int tx = threadIdx.x, ty = threadIdx.y;
    #pragma unroll
    for (int r = 0; r < 4; r++) {
        int i = ty + r * 8;
        int l = lt + tx;
        int lp;
        if      (d == 0) lp = l;
        else if (d == 1) lp = 4095 - l;
        else if (d == 2) lp = (l & 63) * 64 + (l >> 6);
        else             { int lv = 4095 - l; lp = (lv & 63) * 64 + (lv >> 6); }
        tile[i][tx] = pts[(mt + i) * Lc + lp];
    }
    __syncthreads();
    #pragma unroll
    for (int r = 0; r < 4; r++) {
        int i = ty + r * 8;
        g_U[(size_t)(d * Lc + lt + i) * DMc + mt + tx] = tile[tx][i];
    }
}

// ---------------- 1. in-proj (double-buffered) ----------------
__global__ void __launch_bounds__(256) k_inproj(const float* __restrict__ Win) {
    int d = blockIdx.z;
    int m0 = blockIdx.x * 128, n0 = blockIdx.y * 128;
    const float* A = g_U + (size_t)d * Lc * DMc + (size_t)m0 * DMc;
    const float* B = Win + (size_t)d * DIPc * DMc + (size_t)n0 * DMc;
    int nrem = DIPc - n0;
    __shared__ float As[2][16][LDT], Bs[2][16][LDT];
    int tid = threadIdx.x, wid = tid >> 5, lane = tid & 31;
    int wm0 = (wid & 1) * 64, wn0 = (wid >> 1) * 32;
    float acc[4][4][4] = {};
    float4 ra[2], rb[2];
    fetch128 (A, DMc, 0, ra, tid);
    fetch128m(B, DMc, 0, nrem, rb, tid);
    store128(ra, As[0], tid); store128(rb, Bs[0], tid);
    __syncthreads();
    const int NT = DMc / 16;
    for (int t = 0; t < NT; t++) {
        int cur = t & 1;
        if (t + 1 < NT) {
            fetch128 (A, DMc, (t + 1) * 16, ra, tid);
            fetch128m(B, DMc, (t + 1) * 16, nrem, rb, tid);
        }
        mma_tile<4,4>(As[cur], Bs[cur], acc, wm0, wn0, lane);
        if (t + 1 < NT) { store128(ra, As[cur ^ 1], tid); store128(rb, Bs[cur ^ 1], tid); }
        __syncthreads();
    }
    int gid = lane >> 2, t4 = lane & 3;
    #pragma unroll
    for (int mi = 0; mi < 4; mi++) {
        int r0 = m0 + wm0 + mi * 16 + gid, r1 = r0 + 8;
        #pragma unroll
        for (int nj = 0; nj < 4; nj++) {
            int c0 = n0 + wn0 + nj * 8 + t4 * 2;
            if (c0 < DIPc) {
                g_Z[(size_t)(d * Lc + r0) * DIPc + c0]     = acc[mi][nj][0];
                g_Z[(size_t)(d * Lc + r0) * DIPc + c0 + 1] = acc[mi][nj][1];
                g_Z[(size_t)(d * Lc + r1) * DIPc + c0]     = acc[mi][nj][2];
                g_Z[(size_t)(d * Lc + r1) * DIPc + c0 + 1] = acc[mi][nj][3];
            }
        }
    }
}

// ---------------- 2. conv1d (register window, each input read once) ----------------
__global__ void __launch_bounds__(256) k_conv(const float* __restrict__ conv_w,
                                              const float* __restrict__ conv_b) {
    int seg = blockIdx.x;        // 16 segments of 256
    int chunk = blockIdx.y;      // 3 chunks of 256 channels
    int d = blockIdx.z;
    int tid = threadIdx.x;
    int ch = chunk * 256 + tid;
    const float* zcol = g_Z + (size_t)(d * Lc) * DIPc + DIc + ch;
    const float* cw = conv_w + (size_t)(d * CDc + ch) * 4;
    float cw0 = cw[0], cw1 = cw[1], cw2 = cw[2], cw3 = cw[3];
    float bb = conv_b[d * CDc + ch];
    int l0 = seg * 256;
    float h0 = (l0 >= 3) ? zcol[(size_t)(l0 - 3) * DIPc] : 0.f;
    float h1 = (l0 >= 2) ? zcol[(size_t)(l0 - 2) * DIPc] : 0.f;
    float h2 = (l0 >= 1) ? zcol[(size_t)(l0 - 1) * DIPc] : 0.f;
    #pragma unroll 4
    for (int l = l0; l < l0 + 256; l++) {
        float cur = zcol[(size_t)l * DIPc];
        float acc = bb + h0 * cw0 + h1 * cw1 + h2 * cw2 + cur * cw3;
        g_xBC[(size_t)(d * Lc + l) * CDc + ch] = silu_f(acc);
        h0 = h1; h1 = h2; h2 = cur;
    }
}

// ---------------- 3. softplus dt + per-chunk cumsum of dt*A ----------------
__global__ void __launch_bounds__(256) k_scan(const float* __restrict__ A_log,
                                              const float* __restrict__ dt_bias) {
    int c = blockIdx.x, h = blockIdx.y, d = blockIdx.z, s = threadIdx.x;
    float A = -__expf(A_log[d * NHc + h]);
    int l = c * CSc + s;
    float v = g_Z[(size_t)(d * Lc + l) * DIPc + (DIc + CDc) + h] + dt_bias[d * NHc + h];
    float sp = (v > 20.f) ? v : log1pf(__expf(v));
    g_dt[(size_t)(d * Lc + l) * NHc + h] = sp;
    __shared__ float buf[256];
    buf[s] = sp * A;
    __syncthreads();
    for (int off = 1; off < 256; off <<= 1) {
        float t = (s >= off) ? buf[s - off] : 0.f;
        __syncthreads();
        buf[s] += t;
        __syncthreads();
    }
    g_dA[(size_t)(d * Lc + l) * NHc + h] = buf[s];
}

// ---------------- 4. CB = C @ B^T (double-buffered) ----------------
__global__ void __launch_bounds__(256) k_cb() {
    int dc = blockIdx.z; int d = dc >> 4, c = dc & 15;
    int i0 = blockIdx.x * 128, j0 = blockIdx.y * 128;
    const float* base = g_xBC + (size_t)(d * Lc + c * CSc) * CDc;
    const float* A = base + (size_t)i0 * CDc + (DIc + DSc);
    const float* B = base + (size_t)j0 * CDc + DIc;
    __shared__ float As[2][16][LDT], Bs[2][16][LDT];
    int tid = threadIdx.x, wid = tid >> 5, lane = tid & 31;
    int wm0 = (wid & 1) * 64, wn0 = (wid >> 1) * 32;
    float acc[4][4][4] = {};
    float4 ra[2], rb[2];
    fetch128(A, CDc, 0, ra, tid); fetch128(B, CDc, 0, rb, tid);
    store128(ra, As[0], tid); store128(rb, Bs[0], tid);
    __syncthreads();
    const int NT = DSc / 16;
    for (int t = 0; t < NT; t++) {
        int cur = t & 1;
        if (t + 1 < NT) {
            fetch128(A, CDc, (t + 1) * 16, ra, tid);
            fetch128(B, CDc, (t + 1) * 16, rb, tid);
        }
        mma_tile<4,4>(As[cur], Bs[cur], acc, wm0, wn0, lane);
        if (t + 1 < NT) { store128(ra, As[cur ^ 1], tid); store128(rb, Bs[cur ^ 1], tid); }
        __syncthreads();
    }
    float* out = g_CB + (size_t)(d * NCc + c) * CSc * CSc;
    int gid = lane >> 2, t4 = lane & 3;
    #pragma unroll
    for (int mi = 0; mi < 4; mi++) {
        int r0 = i0 + wm0 + mi * 16 + gid, r1 = r0 + 8;
        #pragma unroll
        for (int nj = 0; nj < 4; nj++) {
            int c0 = j0 + wn0 + nj * 8 + t4 * 2;
            out[r0 * CSc + c0]     = acc[mi][nj][0];
            out[r0 * CSc + c0 + 1] = acc[mi][nj][1];
            out[r1 * CSc + c0]     = acc[mi][nj][2];
            out[r1 * CSc + c0 + 1] = acc[mi][nj][3];
        }
    }
}

// ---------------- 5. states[p][n] ----------------
__global__ void __launch_bounds__(256) k_states() {
    int z = blockIdx.z; int d = z >> 7, c = (z >> 3) & 15, h = z & 7;
    __shared__ float Aw[16][LDT], Bsh[16][LDT];
    __shared__ float daF[256], dtF[256];
    int tid = threadIdx.x, wid = tid >> 5, lane = tid & 31;
    int wm0 = (wid & 1) * 32, wn0 = (wid >> 1) * 32;
    daF[tid] = g_dA[(size_t)(d * Lc + c * CSc + tid) * NHc + h];
    dtF[tid] = g_dt[(size_t)(d * Lc + c * CSc + tid) * NHc + h];
    __syncthreads();
    float daL = daF[255];
    const float* base = g_xBC + (size_t)(d * Lc + c * CSc) * CDc;
    float acc[2][4][4] = {};
    for (int s0 = 0; s0 < CSc; s0 += 16) {
        {
            int e = tid * 4; int col = e & 63; int ss = e >> 6;
            float w = dtF[s0 + ss] * __expf(daL - daF[s0 + ss]);
            float4 v = *(const float4*)(base + (size_t)(s0 + ss) * CDc + h * HDc + col);
            Aw[ss][col] = f2tf(v.x*w); Aw[ss][col+1] = f2tf(v.y*w);
            Aw[ss][col+2] = f2tf(v.z*w); Aw[ss][col+3] = f2tf(v.w*w);
        }
        #pragma unroll
        for (int hh = 0; hh < 2; hh++) {
            int e = tid * 4 + hh * 1024; int col = e & 127; int ss = e >> 7;
            float4 v = *(const float4*)(base + (size_t)(s0 + ss) * CDc + DIc + col);
            Bsh[ss][col] = f2tf(v.x); Bsh[ss][col+1] = f2tf(v.y);
            Bsh[ss][col+2] = f2tf(v.z); Bsh[ss][col+3] = f2tf(v.w);
        }
        __syncthreads();
        mma_tile<2,4>(Aw, Bsh, acc, wm0, wn0, lane);
        __syncthreads();
    }
    float* out = g_st + (size_t)((d * NCc + c) * NHc + h) * HDc * DSc;
    int gid = lane >> 2, t4 = lane & 3;
    #pragma unroll
    for (int mi = 0; mi < 2; mi++) {
        int r0 = wm0 + mi * 16 + gid, r1 = r0 + 8;
        #pragma unroll
        for (int nj = 0; nj < 4; nj++) {
            int c0 = wn0 + nj * 8 + t4 * 2;
            out[r0 * DSc + c0]     = acc[mi][nj][0];
            out[r0 * DSc + c0 + 1] = acc[mi][nj][1];
            out[r1 * DSc + c0]     = acc[mi][nj][2];
            out[r1 * DSc + c0 + 1] = acc[mi][nj][3];
        }
    }
}

// ---------------- 6. inter-chunk scan ----------------
__global__ void __launch_bounds__(256) k_chunkscan() {
    int dh = blockIdx.x; int d = dh >> 3, h = dh & 7;
    int tid = threadIdx.x;
    float carry[32];
    #pragma unroll
    for (int t = 0; t < 32; t++) carry[t] = 0.f;
    for (int c = 0; c < NCc; c++) {
        float cd = __expf(g_dA[(size_t)(d * Lc + c * CSc + 255) * NHc + h]);
        size_t off = (size_t)((d * NCc + c) * NHc + h) * 8192;
        #pragma unroll
        for (int t = 0; t < 32; t++) {
            int e = tid + t * 256;
            g_pv[off + e] = carry[t];
            carry[t] = carry[t] * cd + g_st[off + e];
        }
    }
}

// ---------------- 7. SSD y + gate + partial sumsq ----------------
__global__ void __launch_bounds__(256) k_ssd_y(const float* __restrict__ D_param) {
    int i0 = blockIdx.x * 128;
    int z  = blockIdx.z; int d = z >> 7, c = (z >> 3) & 15, h = z & 7;
    __shared__ float Ss[16][LDT], Xs[16][LDT];
    __shared__ float daF[256], dtF[256], eI[128];
    int tid = threadIdx.x, wid = tid >> 5, lane = tid & 31;
    int wm0 = (wid & 3) * 32, wn0 = (wid >> 2) * 32;
    daF[tid] = g_dA[(size_t)(d * Lc + c * CSc + tid) * NHc + h];
    dtF[tid] = g_dt[(size_t)(d * Lc + c * CSc + tid) * NHc + h];
    __syncthreads();
    if (tid < 128) eI[tid] = __expf(daF[i0 + tid]);
    __syncthreads();
    const float* cbb   = g_CB + (size_t)(d * NCc + c) * CSc * CSc;
    const float* base  = g_xBC + (size_t)(d * Lc + c * CSc) * CDc;
    const float* xbase = base + h * HDc;
    float acc[2][4][4] = {};
    for (int j0 = 0; j0 < CSc; j0 += 16) {
        #pragma unroll
        for (int hh = 0; hh < 2; hh++) {
            int e = tid * 4 + hh * 1024; int kk = e & 15; int ii = e >> 4;
            float4 v = *(const float4*)(cbb + (i0 + ii) * CSc + j0 + kk);
            float r[4] = {v.x, v.y, v.z, v.w};
            float dai = daF[i0 + ii];
            int ig = i0 + ii;
            #pragma unroll
            for (int q = 0; q < 4; q++) {
                int jg = j0 + kk + q;
                float sv = 0.f;
                if (jg <= ig) sv = r[q] * __expf(dai - daF[jg]) * dtF[jg];
                Ss[kk + q][ii] = f2tf(sv);
            }
        }
        {
            int e = tid * 4; int p = e & 63; int jj = e >> 6;
            float4 v = *(const float4*)(xbase + (size_t)(j0 + jj) * CDc + p);
            Xs[jj][p] = f2tf(v.x); Xs[jj][p+1] = f2tf(v.y);
            Xs[jj][p+2] = f2tf(v.z); Xs[jj][p+3] = f2tf(v.w);
        }
        __syncthreads();
        mma_tile<2,4>(Ss, Xs, acc, wm0, wn0, lane);
        __syncthreads();
    }
    const float* Cb = base + (size_t)i0 * CDc + (DIc + DSc);
    const float* pv = g_pv + (size_t)((d * NCc + c) * NHc + h) * HDc * DSc;
    for (int k0 = 0; k0 < DSc; k0 += 16) {
        #pragma unroll
        for (int hh = 0; hh < 2; hh++) {
            int e = tid * 4 + hh * 1024; int kk = e & 15; int ii = e >> 4;
            float4 v = *(const float4*)(Cb + (size_t)ii * CDc + k0 + kk);
            float ei = eI[ii];
            Ss[kk][ii]   = f2tf(v.x * ei); Ss[kk+1][ii] = f2tf(v.y * ei);
            Ss[kk+2][ii] = f2tf(v.z * ei); Ss[kk+3][ii] = f2tf(v.w * ei);
        }
        {
            int e = tid * 4; int kk = e & 15; int rr = e >> 4;
            float4 v = *(const float4*)(pv + (size_t)rr * DSc + k0 + kk);
            Xs[kk][rr] = f2tf(v.x); Xs[kk+1][rr] = f2tf(v.y);
            Xs[kk+2][rr] = f2tf(v.z); Xs[kk+3][rr] = f2tf(v.w);
        }
        __syncthreads();
        mma_tile<2,4>(Ss, Xs, acc, wm0, wn0, lane);
        __syncthreads();
    }
    float Dh = D_param[d * NHc + h];
    int gid = lane >> 2, t4 = lane & 3;
    int half = wn0 >> 5;
    #pragma unroll
    for (int mi = 0; mi < 2; mi++) {
        int lr0 = wm0 + mi * 16 + gid, lr1 = lr0 + 8;
        int l0 = c * CSc + i0 + lr0, l1 = c * CSc + i0 + lr1;
        float s0 = 0.f, s1 = 0.f;
        #pragma unroll
        for (int nj = 0; nj < 4; nj++) {
            int p0 = wn0 + nj * 8 + t4 * 2;
            size_t y0 = (size_t)(d * Lc + l0) * DIc + h * HDc + p0;
            size_t y1 = (size_t)(d * Lc + l1) * DIc + h * HDc + p0;
            size_t x0 = (size_t)(d * Lc + l0) * CDc + h * HDc + p0;
            size_t x1 = (size_t)(d * Lc + l1) * CDc + h * HDc + p0;
            size_t z0 = (size_t)(d * Lc + l0) * DIPc + h * HDc + p0;
            size_t z1 = (size_t)(d * Lc + l1) * DIPc + h * HDc + p0;
            float v00 = (acc[mi][nj][0] + Dh * g_xBC[x0])     * silu_f(g_Z[z0]);
            float v01 = (acc[mi][nj][1] + Dh * g_xBC[x0 + 1]) * silu_f(g_Z[z0 + 1]);
            float v10 = (acc[mi][nj][2] + Dh * g_xBC[x1])     * silu_f(g_Z[z1]);
            float v11 = (acc[mi][nj][3] + Dh * g_xBC[x1 + 1]) * silu_f(g_Z[z1 + 1]);
            g_y[y0] = v00; g_y[y0 + 1] = v01;
            g_y[y1] = v10; g_y[y1 + 1] = v11;
            s0 += v00 * v00 + v01 * v01;
            s1 += v10 * v10 + v11 * v11;
        }
        // reduce across the 4 t4-lanes sharing this row
        s0 += __shfl_xor_sync(0xffffffffu, s0, 1);
        s0 += __shfl_xor_sync(0xffffffffu, s0, 2);
        s1 += __shfl_xor_sync(0xffffffffu, s1, 1);
        s1 += __shfl_xor_sync(0xffffffffu, s1, 2);
        if (t4 == 0) {
            g_ssp[(size_t)(d * Lc + l0) * 16 + h * 2 + half] = s0;
            g_ssp[(size_t)(d * Lc + l1) * 16 + h * 2 + half] = s1;
        }
    }
}

// ---------------- 8. out-proj (fused RMSNorm on A) + permuted scatter ----------------
__global__ void __launch_bounds__(256) k_outproj(const float* __restrict__ Wout,
                                                 const float* __restrict__ norm_w) {
    int d = blockIdx.z;
    int m0 = blockIdx.x * 128, n0 = blockIdx.y * 128;
    const float* A = g_y + (size_t)d * Lc * DIc + (size_t)m0 * DIc;
    const float* B = Wout + (size_t)d * DMc * DIc + (size_t)n0 * DIc;
    __shared__ float As[2][16][LDT], Bs[2][16][LDT];
    __shared__ float rs[128], nwsm[DIc];
    int tid = threadIdx.x, wid = tid >> 5, lane = tid & 31;
    int wm0 = (wid & 1) * 64, wn0 = (wid >> 1) * 32;
    // pre-pass: row scales + norm_w
    #pragma unroll
    for (int i = tid; i < DIc; i += 256) nwsm[i] = norm_w[d * DIc + i];
    if (tid < 128) {
        const float* pp = g_ssp + (size_t)(d * Lc + m0 + tid) * 16;
        float s = 0.f;
        #pragma unroll
        for (int i = 0; i < 16; i++) s += pp[i];
        rs[tid] = rsqrtf(s / (float)DIc + EPSc);
    }
    __syncthreads();
    float acc[4][4][4] = {};
    float4 ra[2], rb[2];
    fetch128(A, DIc, 0, ra, tid); fetch128(B, DIc, 0, rb, tid);
    store128n(ra, As[0], tid, rs, nwsm, 0); store128(rb, Bs[0], tid);
    __syncthreads();
    const int NT = DIc / 16;
    for (int t = 0; t < NT; t++) {
        int cur = t & 1;
        if (t + 1 < NT) {
            fetch128(A, DIc, (t + 1) * 16, ra, tid);
            fetch128(B, DIc, (t + 1) * 16, rb, tid);
        }
        mma_tile<4,4>(As[cur], Bs[cur], acc, wm0, wn0, lane);
        if (t + 1 < NT) {
            store128n(ra, As[cur ^ 1], tid, rs, nwsm, (t + 1) * 16);
            store128(rb, Bs[cur ^ 1], tid);
        }
        __syncthreads();
    }
    int gid = lane >> 2, t4 = lane & 3;
    #pragma unroll
    for (int mi = 0; mi < 4; mi++) {
        #pragma unroll
        for (int half = 0; half < 2; half++) {
            int l = m0 + wm0 + mi * 16 + gid + half * 8;
            int r;
            if      (d == 0) r = l;
            else if (d == 1) r = 4095 - l;
            else if (d == 2) r = (l & 63) * 64 + (l >> 6);
            else             { int lv = 4095 - l; r = (lv & 63) * 64 + (lv >> 6); }
            #pragma unroll
            for (int nj = 0; nj < 4; nj++) {
                int c0 = n0 + wn0 + nj * 8 + t4 * 2;
                g_cat[(size_t)r * (4 * DMc) + d * DMc + c0]     = acc[mi][nj][half * 2];
                g_cat[(size_t)r * (4 * DMc) + d * DMc + c0 + 1] = acc[mi][nj][half * 2 + 1];
            }
        }
    }
}

// ---------------- 9. final GEMM (double-buffered, SiLU fused on A) ----------------
__global__ void __launch_bounds__(256) k_final(const float* __restrict__ Wf,
                                               float* __restrict__ out) {
    int m0 = blockIdx.x * 128, n0 = blockIdx.y * 64;
    const float* A = g_cat + (size_t)m0 * 1024;
    const float* B = Wf + (size_t)n0 * 1024;
    __shared__ float As[2][16][LDT], Bs[2][16][LDT];
    int tid = threadIdx.x, wid = tid >> 5, lane = tid & 31;
    int wm0 = (wid & 3) * 32, wn0 = (wid >> 2) * 32;
    float acc[2][4][4] = {};
    float4 ra[2], rb;
    fetch128(A, 1024, 0, ra, tid); fetch64(B, 1024, 0, rb, tid);
    store128s(ra, As[0], tid); store64(rb, Bs[0], tid);
    __syncthreads();
    const int NT = 1024 / 16;
    for (int t = 0; t < NT; t++) {
        int cur = t & 1;
        if (t + 1 < NT) {
            fetch128(A, 1024, (t + 1) * 16, ra, tid);
            fetch64 (B, 1024, (t + 1) * 16, rb, tid);
        }
        mma_tile<2,4>(As[cur], Bs[cur], acc, wm0, wn0, lane);
        if (t + 1 < NT) { store128s(ra, As[cur ^ 1], tid); store64(rb, Bs[cur ^ 1], tid); }
        __syncthreads();
    }
    int gid = lane >> 2, t4 = lane & 3;
    #pragma unroll
    for (int mi = 0; mi < 2; mi++) {
        int r0 = m0 + wm0 + mi * 16 + gid, r1 = r0 + 8;
        #pragma unroll
        for (int nj = 0; nj < 4; nj++) {
            int c0 = n0 + wn0 + nj * 8 + t4 * 2;
            out[(size_t)r0 * DMc + c0]     = acc[mi][nj][0];
            out[(size_t)r0 * DMc + c0 + 1] = acc[mi][nj][1];
            out[(size_t)r1 * DMc + c0]     = acc[mi][nj][2];
            out[(size_t)r1 * DMc + c0 + 1] = acc[mi][nj][3];
        }
    }
}

// ---------------- launcher ----------------
extern "C" void kernel_launch(void* const* d_in, const int* in_sizes, int n_in,
                              void* d_out, int out_size) {
    const float* pts      = (const float*)d_in[0];
    const float* in_proj  = (const float*)d_in[2];
    const float* conv_w   = (const float*)d_in[3];
    const float* conv_b   = (const float*)d_in[4];
    const float* dt_bias  = (const float*)d_in[5];
    const float* A_log    = (const float*)d_in[6];
    const float* D_param  = (const float*)d_in[7];
    const float* norm_w   = (const float*)d_in[8];
    const float* outp_w   = (const float*)d_in[9];
    const float* final_w  = (const float*)d_in[10];
    float* out = (float*)d_out;

    k_buildU   <<<dim3(128, 8, 4), dim3(32, 8)>>>(pts);
    k_inproj   <<<dim3(32, 11, 4), 256>>>(in_proj);
    k_conv     <<<dim3(16, 3, 4),  256>>>(conv_w, conv_b);
    k_scan     <<<dim3(16, 8, 4),  256>>>(A_log, dt_bias);
    k_cb       <<<dim3(2, 2, 64),  256>>>();
    k_states   <<<dim3(1, 1, 512), 256>>>();
    k_chunkscan<<<32, 256>>>();
    k_ssd_y    <<<dim3(2, 1, 512), 256>>>(D_param);
    k_outproj  <<<dim3(32, 2, 4),  256>>>(outp_w, norm_w);
    k_final    <<<dim3(32, 4),     256>>>(final_w, out);
}

// round 16
// speedup vs baseline: 1.1715x; 1.1715x over previous
#include <cuda_runtime.h>
#include <math.h>

// ---------------- problem constants ----------------
#define DMc   256
#define Lc    4096
#define DSc   128
#define DIc   512
#define NHc   8
#define HDc   64
#define CDc   768
#define DIPc  1288
#define CSc   256
#define NCc   16
#define EPSc  1e-5f
#define LDT   136

// ---------------- device scratch ----------------
__device__ float g_U  [4 * Lc * DMc];
__device__ float g_Z  [4 * Lc * DIPc];
__device__ float g_xBC[4 * Lc * CDc];
__device__ float g_dt [4 * Lc * NHc];
__device__ float g_dA [4 * Lc * NHc];
__device__ float g_CB [4 * NCc * CSc * CSc];
__device__ float g_y  [4 * Lc * DIc];          // gated (y_total * silu(z)), pre-norm
__device__ float g_ssp[4 * Lc * 16];           // partial sum-squares per row: 8 heads x 2 halves
__device__ float g_st [4 * NCc * NHc * HDc * DSc];
__device__ float g_pv [4 * NCc * NHc * HDc * DSc];
__device__ float g_cat[Lc * 4 * DMc];

__device__ __forceinline__ float silu_f(float x) { return x / (1.f + __expf(-x)); }

// ---------------- tf32 helpers ----------------
__device__ __forceinline__ unsigned f2t(float x) {
    unsigned r; asm("cvt.rna.tf32.f32 %0, %1;" : "=r"(r) : "f"(x)); return r;
}
__device__ __forceinline__ float f2tf(float x) { return __uint_as_float(f2t(x)); }

__device__ __forceinline__ void mma_tf32(float& d0, float& d1, float& d2, float& d3,
                                         unsigned a0, unsigned a1, unsigned a2, unsigned a3,
                                         unsigned b0, unsigned b1) {
    asm volatile("mma.sync.aligned.m16n8k8.row.col.f32.tf32.tf32.f32 "
                 "{%0,%1,%2,%3}, {%4,%5,%6,%7}, {%8,%9}, {%0,%1,%2,%3};\n"
                 : "+f"(d0), "+f"(d1), "+f"(d2), "+f"(d3)
                 : "r"(a0), "r"(a1), "r"(a2), "r"(a3), "r"(b0), "r"(b1));
}

template<int MF, int NF>
__device__ __forceinline__ void mma_tile(const float (*As)[LDT], const float (*Bs)[LDT],
                                         float acc[MF][NF][4], int wm0, int wn0, int lane) {
    int gid = lane >> 2, t4 = lane & 3;
    #pragma unroll
    for (int ks = 0; ks < 16; ks += 8) {
        unsigned a[MF][4], b[NF][2];
        #pragma unroll
        for (int mi = 0; mi < MF; mi++) {
            int m = wm0 + mi * 16 + gid;
            a[mi][0] = __float_as_uint(As[ks + t4    ][m]);
            a[mi][1] = __float_as_uint(As[ks + t4    ][m + 8]);
            a[mi][2] = __float_as_uint(As[ks + t4 + 4][m]);
            a[mi][3] = __float_as_uint(As[ks + t4 + 4][m + 8]);
        }
        #pragma unroll
        for (int nj = 0; nj < NF; nj++) {
            int n = wn0 + nj * 8 + gid;
            b[nj][0] = __float_as_uint(Bs[ks + t4    ][n]);
            b[nj][1] = __float_as_uint(Bs[ks + t4 + 4][n]);
        }
        #pragma unroll
        for (int mi = 0; mi < MF; mi++)
            #pragma unroll
            for (int nj = 0; nj < NF; nj++)
                mma_tf32(acc[mi][nj][0], acc[mi][nj][1], acc[mi][nj][2], acc[mi][nj][3],
                         a[mi][0], a[mi][1], a[mi][2], a[mi][3], b[nj][0], b[nj][1]);
    }
}

// ======== register-staged fetch / smem store (BK=16) ========
__device__ __forceinline__ void fetch128(const float* __restrict__ G, int ld, int k0,
                                         float4 r[2], int tid) {
    #pragma unroll
    for (int h = 0; h < 2; h++) {
        int e = tid * 4 + h * 1024; int kk = e & 15; int rr = e >> 4;
        r[h] = *(const float4*)(G + (size_t)rr * ld + k0 + kk);
    }
}
__device__ __forceinline__ void fetch128m(const float* __restrict__ G, int ld, int k0, int rlim,
                                          float4 r[2], int tid) {
    #pragma unroll
    for (int h = 0; h < 2; h++) {
        int e = tid * 4 + h * 1024; int kk = e & 15; int rr = e >> 4;
        r[h] = make_float4(0.f, 0.f, 0.f, 0.f);
        if (rr < rlim) r[h] = *(const float4*)(G + (size_t)rr * ld + k0 + kk);
    }
}
__device__ __forceinline__ void store128(const float4 r[2], float (*S)[LDT], int tid) {
    #pragma unroll
    for (int h = 0; h < 2; h++) {
        int e = tid * 4 + h * 1024; int kk = e & 15; int rr = e >> 4;
        S[kk][rr] = f2tf(r[h].x); S[kk+1][rr] = f2tf(r[h].y);
        S[kk+2][rr] = f2tf(r[h].z); S[kk+3][rr] = f2tf(r[h].w);
    }
}
__device__ __forceinline__ void store128s(const float4 r[2], float (*S)[LDT], int tid) {
    #pragma unroll
    for (int h = 0; h < 2; h++) {
        int e = tid * 4 + h * 1024; int kk = e & 15; int rr = e >> 4;
        S[kk][rr] = f2tf(silu_f(r[h].x)); S[kk+1][rr] = f2tf(silu_f(r[h].y));
        S[kk+2][rr] = f2tf(silu_f(r[h].z)); S[kk+3][rr] = f2tf(silu_f(r[h].w));
    }
}
// normalized store: v * rowScale[rr] * norm_w[k]
__device__ __forceinline__ void store128n(const float4 r[2], float (*S)[LDT], int tid,
                                          const float* rs, const float* nw, int k0) {
    #pragma unroll
    for (int h = 0; h < 2; h++) {
        int e = tid * 4 + h * 1024; int kk = e & 15; int rr = e >> 4;
        float sc = rs[rr];
        S[kk][rr]   = f2tf(r[h].x * sc * nw[k0 + kk]);
        S[kk+1][rr] = f2tf(r[h].y * sc * nw[k0 + kk + 1]);
        S[kk+2][rr] = f2tf(r[h].z * sc * nw[k0 + kk + 2]);
        S[kk+3][rr] = f2tf(r[h].w * sc * nw[k0 + kk + 3]);
    }
}
__device__ __forceinline__ void fetch64(const float* __restrict__ G, int ld, int k0,
                                        float4& r, int tid) {
    int e = tid * 4; int kk = e & 15; int rr = e >> 4;
    r = *(const float4*)(G + (size_t)rr * ld + k0 + kk);
}
__device__ __forceinline__ void store64(const float4 r, float (*S)[LDT], int tid) {
    int e = tid * 4; int kk = e & 15; int rr = e >> 4;
    S[kk][rr] = f2tf(r.x); S[kk+1][rr] = f2tf(r.y);
    S[kk+2][rr] = f2tf(r.z); S[kk+3][rr] = f2tf(r.w);
}

// ---------------- 0. gather + transpose ----------------
__global__ void k_buildU(const float* __restrict__ pts) {
    int d  = blockIdx.z;
    int lt = blockIdx.x * 32;
    int mt = blockIdx.y * 32;
    __shared__ float tile[32][33];
    int tx = threadIdx.x, ty = threadIdx.y;
    #pragma unroll
    for (int r = 0; r < 4; r++) {
        int i = ty + r * 8;
        int l = lt + tx;
        int lp;
        if      (d == 0) lp = l;
        else if (d == 1) lp = 4095 - l;
        else if (d == 2) lp = (l & 63) * 64 + (l >> 6);
        else             { int lv = 4095 - l; lp = (lv & 63) * 64 + (lv >> 6); }
        tile[i][tx] = pts[(mt + i) * Lc + lp];
    }
    __syncthreads();
    #pragma unroll
    for (int r = 0; r < 4; r++) {
        int i = ty + r * 8;
        g_U[(size_t)(d * Lc + lt + i) * DMc + mt + tx] = tile[tx][i];
    }
}

// ---------------- 1. in-proj (double-buffered) ----------------
__global__ void __launch_bounds__(256) k_inproj(const float* __restrict__ Win) {
    int d = blockIdx.z;
    int m0 = blockIdx.x * 128, n0 = blockIdx.y * 128;
    const float* A = g_U + (size_t)d * Lc * DMc + (size_t)m0 * DMc;
    const float* B = Win + (size_t)d * DIPc * DMc + (size_t)n0 * DMc;
    int nrem = DIPc - n0;
    __shared__ float As[2][16][LDT], Bs[2][16][LDT];
    int tid = threadIdx.x, wid = tid >> 5, lane = tid & 31;
    int wm0 = (wid & 1) * 64, wn0 = (wid >> 1) * 32;
    float acc[4][4][4] = {};
    float4 ra[2], rb[2];
    fetch128 (A, DMc, 0, ra, tid);
    fetch128m(B, DMc, 0, nrem, rb, tid);
    store128(ra, As[0], tid); store128(rb, Bs[0], tid);
    __syncthreads();
    const int NT = DMc / 16;
    for (int t = 0; t < NT; t++) {
        int cur = t & 1;
        if (t + 1 < NT) {
            fetch128 (A, DMc, (t + 1) * 16, ra, tid);
            fetch128m(B, DMc, (t + 1) * 16, nrem, rb, tid);
        }
        mma_tile<4,4>(As[cur], Bs[cur], acc, wm0, wn0, lane);
        if (t + 1 < NT) { store128(ra, As[cur ^ 1], tid); store128(rb, Bs[cur ^ 1], tid); }
        __syncthreads();
    }
    int gid = lane >> 2, t4 = lane & 3;
    #pragma unroll
    for (int mi = 0; mi < 4; mi++) {
        int r0 = m0 + wm0 + mi * 16 + gid, r1 = r0 + 8;
        #pragma unroll
        for (int nj = 0; nj < 4; nj++) {
            int c0 = n0 + wn0 + nj * 8 + t4 * 2;
            if (c0 < DIPc) {
                g_Z[(size_t)(d * Lc + r0) * DIPc + c0]     = acc[mi][nj][0];
                g_Z[(size_t)(d * Lc + r0) * DIPc + c0 + 1] = acc[mi][nj][1];
                g_Z[(size_t)(d * Lc + r1) * DIPc + c0]     = acc[mi][nj][2];
                g_Z[(size_t)(d * Lc + r1) * DIPc + c0 + 1] = acc[mi][nj][3];
            }
        }
    }
}

// ---------------- 2. conv1d + silu ; softplus dt (R13 form: coalesced, high TLP) ----------------
__global__ void __launch_bounds__(256) k_conv(const float* __restrict__ conv_w,
                                              const float* __restrict__ conv_b,
                                              const float* __restrict__ dt_bias) {
    int l = blockIdx.x, d = blockIdx.y, tid = threadIdx.x;
    for (int ch = tid; ch < CDc; ch += 256) {
        float acc = conv_b[d * CDc + ch];
        const float* cw = conv_w + (size_t)(d * CDc + ch) * 4;
        #pragma unroll
        for (int w = 0; w < 4; w++) {
            int ls = l - 3 + w;
            if (ls >= 0)
                acc += g_Z[(size_t)(d * Lc + ls) * DIPc + DIc + ch] * cw[w];
        }
        g_xBC[(size_t)(d * Lc + l) * CDc + ch] = silu_f(acc);
    }
    if (tid < NHc) {
        float v = g_Z[(size_t)(d * Lc + l) * DIPc + (DIc + CDc) + tid] + dt_bias[d * NHc + tid];
        float sp = (v > 20.f) ? v : log1pf(__expf(v));
        g_dt[(size_t)(d * Lc + l) * NHc + tid] = sp;
    }
}

// ---------------- 3. per-chunk cumsum of dt*A (R13 form) ----------------
__global__ void __launch_bounds__(256) k_scan(const float* __restrict__ A_log) {
    int c = blockIdx.x, h = blockIdx.y, d = blockIdx.z, s = threadIdx.x;
    float A = -__expf(A_log[d * NHc + h]);
    __shared__ float buf[256];
    buf[s] = g_dt[(size_t)(d * Lc + c * CSc + s) * NHc + h] * A;
    __syncthreads();
    for (int off = 1; off < 256; off <<= 1) {
        float t = (s >= off) ? buf[s - off] : 0.f;
        __syncthreads();
        buf[s] += t;
        __syncthreads();
    }
    g_dA[(size_t)(d * Lc + c * CSc + s) * NHc + h] = buf[s];
}

// ---------------- 4. CB = C @ B^T (double-buffered) ----------------
__global__ void __launch_bounds__(256) k_cb() {
    int dc = blockIdx.z; int d = dc >> 4, c = dc & 15;
    int i0 = blockIdx.x * 128, j0 = blockIdx.y * 128;
    const float* base = g_xBC + (size_t)(d * Lc + c * CSc) * CDc;
    const float* A = base + (size_t)i0 * CDc + (DIc + DSc);
    const float* B = base + (size_t)j0 * CDc + DIc;
    __shared__ float As[2][16][LDT], Bs[2][16][LDT];
    int tid = threadIdx.x, wid = tid >> 5, lane = tid & 31;
    int wm0 = (wid & 1) * 64, wn0 = (wid >> 1) * 32;
    float acc[4][4][4] = {};
    float4 ra[2], rb[2];
    fetch128(A, CDc, 0, ra, tid); fetch128(B, CDc, 0, rb, tid);
    store128(ra, As[0], tid); store128(rb, Bs[0], tid);
    __syncthreads();
    const int NT = DSc / 16;
    for (int t = 0; t < NT; t++) {
        int cur = t & 1;
        if (t + 1 < NT) {
            fetch128(A, CDc, (t + 1) * 16, ra, tid);
            fetch128(B, CDc, (t + 1) * 16, rb, tid);
        }
        mma_tile<4,4>(As[cur], Bs[cur], acc, wm0, wn0, lane);
        if (t + 1 < NT) { store128(ra, As[cur ^ 1], tid); store128(rb, Bs[cur ^ 1], tid); }
        __syncthreads();
    }
    float* out = g_CB + (size_t)(d * NCc + c) * CSc * CSc;
    int gid = lane >> 2, t4 = lane & 3;
    #pragma unroll
    for (int mi = 0; mi < 4; mi++) {
        int r0 = i0 + wm0 + mi * 16 + gid, r1 = r0 + 8;
        #pragma unroll
        for (int nj = 0; nj < 4; nj++) {
            int c0 = j0 + wn0 + nj * 8 + t4 * 2;
            out[r0 * CSc + c0]     = acc[mi][nj][0];
            out[r0 * CSc + c0 + 1] = acc[mi][nj][1];
            out[r1 * CSc + c0]     = acc[mi][nj][2];
            out[r1 * CSc + c0 + 1] = acc[mi][nj][3];
        }
    }
}

// ---------------- 5. states[p][n] ----------------
__global__ void __launch_bounds__(256) k_states() {
    int z = blockIdx.z; int d = z >> 7, c = (z >> 3) & 15, h = z & 7;
    __shared__ float Aw[16][LDT], Bsh[16][LDT];
    __shared__ float daF[256], dtF[256];
    int tid = threadIdx.x, wid = tid >> 5, lane = tid & 31;
    int wm0 = (wid & 1) * 32, wn0 = (wid >> 1) * 32;
    daF[tid] = g_dA[(size_t)(d * Lc + c * CSc + tid) * NHc + h];
    dtF[tid] = g_dt[(size_t)(d * Lc + c * CSc + tid) * NHc + h];
    __syncthreads();
    float daL = daF[255];
    const float* base = g_xBC + (size_t)(d * Lc + c * CSc) * CDc;
    float acc[2][4][4] = {};
    for (int s0 = 0; s0 < CSc; s0 += 16) {
        {
            int e = tid * 4; int col = e & 63; int ss = e >> 6;
            float w = dtF[s0 + ss] * __expf(daL - daF[s0 + ss]);
            float4 v = *(const float4*)(base + (size_t)(s0 + ss) * CDc + h * HDc + col);
            Aw[ss][col] = f2tf(v.x*w); Aw[ss][col+1] = f2tf(v.y*w);
            Aw[ss][col+2] = f2tf(v.z*w); Aw[ss][col+3] = f2tf(v.w*w);
        }
        #pragma unroll
        for (int hh = 0; hh < 2; hh++) {
            int e = tid * 4 + hh * 1024; int col = e & 127; int ss = e >> 7;
            float4 v = *(const float4*)(base + (size_t)(s0 + ss) * CDc + DIc + col);
            Bsh[ss][col] = f2tf(v.x); Bsh[ss][col+1] = f2tf(v.y);
            Bsh[ss][col+2] = f2tf(v.z); Bsh[ss][col+3] = f2tf(v.w);
        }
        __syncthreads();
        mma_tile<2,4>(Aw, Bsh, acc, wm0, wn0, lane);
        __syncthreads();
    }
    float* out = g_st + (size_t)((d * NCc + c) * NHc + h) * HDc * DSc;
    int gid = lane >> 2, t4 = lane & 3;
    #pragma unroll
    for (int mi = 0; mi < 2; mi++) {
        int r0 = wm0 + mi * 16 + gid, r1 = r0 + 8;
        #pragma unroll
        for (int nj = 0; nj < 4; nj++) {
            int c0 = wn0 + nj * 8 + t4 * 2;
            out[r0 * DSc + c0]     = acc[mi][nj][0];
            out[r0 * DSc + c0 + 1] = acc[mi][nj][1];
            out[r1 * DSc + c0]     = acc[mi][nj][2];
            out[r1 * DSc + c0 + 1] = acc[mi][nj][3];
        }
    }
}

// ---------------- 6. inter-chunk scan ----------------
__global__ void __launch_bounds__(256) k_chunkscan() {
    int dh = blockIdx.x; int d = dh >> 3, h = dh & 7;
    int tid = threadIdx.x;
    float carry[32];
    #pragma unroll
    for (int t = 0; t < 32; t++) carry[t] = 0.f;
    for (int c = 0; c < NCc; c++) {
        float cd = __expf(g_dA[(size_t)(d * Lc + c * CSc + 255) * NHc + h]);
        size_t off = (size_t)((d * NCc + c) * NHc + h) * 8192;
        #pragma unroll
        for (int t = 0; t < 32; t++) {
            int e = tid + t * 256;
            g_pv[off + e] = carry[t];
            carry[t] = carry[t] * cd + g_st[off + e];
        }
    }
}

// ---------------- 7. SSD y + gate + partial sumsq ----------------
__global__ void __launch_bounds__(256) k_ssd_y(const float* __restrict__ D_param) {
    int i0 = blockIdx.x * 128;
    int z  = blockIdx.z; int d = z >> 7, c = (z >> 3) & 15, h = z & 7;
    __shared__ float Ss[16][LDT], Xs[16][LDT];
    __shared__ float daF[256], dtF[256], eI[128];
    int tid = threadIdx.x, wid = tid >> 5, lane = tid & 31;
    int wm0 = (wid & 3) * 32, wn0 = (wid >> 2) * 32;
    daF[tid] = g_dA[(size_t)(d * Lc + c * CSc + tid) * NHc + h];
    dtF[tid] = g_dt[(size_t)(d * Lc + c * CSc + tid) * NHc + h];
    __syncthreads();
    if (tid < 128) eI[tid] = __expf(daF[i0 + tid]);
    __syncthreads();
    const float* cbb   = g_CB + (size_t)(d * NCc + c) * CSc * CSc;
    const float* base  = g_xBC + (size_t)(d * Lc + c * CSc) * CDc;
    const float* xbase = base + h * HDc;
    float acc[2][4][4] = {};
    for (int j0 = 0; j0 < CSc; j0 += 16) {
        #pragma unroll
        for (int hh = 0; hh < 2; hh++) {
            int e = tid * 4 + hh * 1024; int kk = e & 15; int ii = e >> 4;
            float4 v = *(const float4*)(cbb + (i0 + ii) * CSc + j0 + kk);
            float r[4] = {v.x, v.y, v.z, v.w};
            float dai = daF[i0 + ii];
            int ig = i0 + ii;
            #pragma unroll
            for (int q = 0; q < 4; q++) {
                int jg = j0 + kk + q;
                float sv = 0.f;
                if (jg <= ig) sv = r[q] * __expf(dai - daF[jg]) * dtF[jg];
                Ss[kk + q][ii] = f2tf(sv);
            }
        }
        {
            int e = tid * 4; int p = e & 63; int jj = e >> 6;
            float4 v = *(const float4*)(xbase + (size_t)(j0 + jj) * CDc + p);
            Xs[jj][p] = f2tf(v.x); Xs[jj][p+1] = f2tf(v.y);
            Xs[jj][p+2] = f2tf(v.z); Xs[jj][p+3] = f2tf(v.w);
        }
        __syncthreads();
        mma_tile<2,4>(Ss, Xs, acc, wm0, wn0, lane);
        __syncthreads();
    }
    const float* Cb = base + (size_t)i0 * CDc + (DIc + DSc);
    const float* pv = g_pv + (size_t)((d * NCc + c) * NHc + h) * HDc * DSc;
    for (int k0 = 0; k0 < DSc; k0 += 16) {
        #pragma unroll
        for (int hh = 0; hh < 2; hh++) {
            int e = tid * 4 + hh * 1024; int kk = e & 15; int ii = e >> 4;
            float4 v = *(const float4*)(Cb + (size_t)ii * CDc + k0 + kk);
            float ei = eI[ii];
            Ss[kk][ii]   = f2tf(v.x * ei); Ss[kk+1][ii] = f2tf(v.y * ei);
            Ss[kk+2][ii] = f2tf(v.z * ei); Ss[kk+3][ii] = f2tf(v.w * ei);
        }
        {
            int e = tid * 4; int kk = e & 15; int rr = e >> 4;
            float4 v = *(const float4*)(pv + (size_t)rr * DSc + k0 + kk);
            Xs[kk][rr] = f2tf(v.x); Xs[kk+1][rr] = f2tf(v.y);
            Xs[kk+2][rr] = f2tf(v.z); Xs[kk+3][rr] = f2tf(v.w);
        }
        __syncthreads();
        mma_tile<2,4>(Ss, Xs, acc, wm0, wn0, lane);
        __syncthreads();
    }
    float Dh = D_param[d * NHc + h];
    int gid = lane >> 2, t4 = lane & 3;
    int half = wn0 >> 5;
    #pragma unroll
    for (int mi = 0; mi < 2; mi++) {
        int lr0 = wm0 + mi * 16 + gid, lr1 = lr0 + 8;
        int l0 = c * CSc + i0 + lr0, l1 = c * CSc + i0 + lr1;
        float s0 = 0.f, s1 = 0.f;
        #pragma unroll
        for (int nj = 0; nj < 4; nj++) {
            int p0 = wn0 + nj * 8 + t4 * 2;
            size_t y0 = (size_t)(d * Lc + l0) * DIc + h * HDc + p0;
            size_t y1 = (size_t)(d * Lc + l1) * DIc + h * HDc + p0;
            size_t x0 = (size_t)(d * Lc + l0) * CDc + h * HDc + p0;
            size_t x1 = (size_t)(d * Lc + l1) * CDc + h * HDc + p0;
            size_t z0 = (size_t)(d * Lc + l0) * DIPc + h * HDc + p0;
            size_t z1 = (size_t)(d * Lc + l1) * DIPc + h * HDc + p0;
            float v00 = (acc[mi][nj][0] + Dh * g_xBC[x0])     * silu_f(g_Z[z0]);
            float v01 = (acc[mi][nj][1] + Dh * g_xBC[x0 + 1]) * silu_f(g_Z[z0 + 1]);
            float v10 = (acc[mi][nj][2] + Dh * g_xBC[x1])     * silu_f(g_Z[z1]);
            float v11 = (acc[mi][nj][3] + Dh * g_xBC[x1 + 1]) * silu_f(g_Z[z1 + 1]);
            g_y[y0] = v00; g_y[y0 + 1] = v01;
            g_y[y1] = v10; g_y[y1 + 1] = v11;
            s0 += v00 * v00 + v01 * v01;
            s1 += v10 * v10 + v11 * v11;
        }
        s0 += __shfl_xor_sync(0xffffffffu, s0, 1);
        s0 += __shfl_xor_sync(0xffffffffu, s0, 2);
        s1 += __shfl_xor_sync(0xffffffffu, s1, 1);
        s1 += __shfl_xor_sync(0xffffffffu, s1, 2);
        if (t4 == 0) {
            g_ssp[(size_t)(d * Lc + l0) * 16 + h * 2 + half] = s0;
            g_ssp[(size_t)(d * Lc + l1) * 16 + h * 2 + half] = s1;
        }
    }
}

// ---------------- 8. out-proj (fused RMSNorm on A) + permuted scatter ----------------
__global__ void __launch_bounds__(256) k_outproj(const float* __restrict__ Wout,
                                                 const float* __restrict__ norm_w) {
    int d = blockIdx.z;
    int m0 = blockIdx.x * 128, n0 = blockIdx.y * 128;
    const float* A = g_y + (size_t)d * Lc * DIc + (size_t)m0 * DIc;
    const float* B = Wout + (size_t)d * DMc * DIc + (size_t)n0 * DIc;
    __shared__ float As[2][16][LDT], Bs[2][16][LDT];
    __shared__ float rs[128], nwsm[DIc];
    int tid = threadIdx.x, wid = tid >> 5, lane = tid & 31;
    int wm0 = (wid & 1) * 64, wn0 = (wid >> 1) * 32;
    #pragma unroll
    for (int i = tid; i < DIc; i += 256) nwsm[i] = norm_w[d * DIc + i];
    if (tid < 128) {
        const float* pp = g_ssp + (size_t)(d * Lc + m0 + tid) * 16;
        float s = 0.f;
        #pragma unroll
        for (int i = 0; i < 16; i++) s += pp[i];
        rs[tid] = rsqrtf(s / (float)DIc + EPSc);
    }
    __syncthreads();
    float acc[4][4][4] = {};
    float4 ra[2], rb[2];
    fetch128(A, DIc, 0, ra, tid); fetch128(B, DIc, 0, rb, tid);
    store128n(ra, As[0], tid, rs, nwsm, 0); store128(rb, Bs[0], tid);
    __syncthreads();
    const int NT = DIc / 16;
    for (int t = 0; t < NT; t++) {
        int cur = t & 1;
        if (t + 1 < NT) {
            fetch128(A, DIc, (t + 1) * 16, ra, tid);
            fetch128(B, DIc, (t + 1) * 16, rb, tid);
        }
        mma_tile<4,4>(As[cur], Bs[cur], acc, wm0, wn0, lane);
        if (t + 1 < NT) {
            store128n(ra, As[cur ^ 1], tid, rs, nwsm, (t + 1) * 16);
            store128(rb, Bs[cur ^ 1], tid);
        }
        __syncthreads();
    }
    int gid = lane >> 2, t4 = lane & 3;
    #pragma unroll
    for (int mi = 0; mi < 4; mi++) {
        #pragma unroll
        for (int half = 0; half < 2; half++) {
            int l = m0 + wm0 + mi * 16 + gid + half * 8;
            int r;
            if      (d == 0) r = l;
            else if (d == 1) r = 4095 - l;
            else if (d == 2) r = (l & 63) * 64 + (l >> 6);
            else             { int lv = 4095 - l; r = (lv & 63) * 64 + (lv >> 6); }
            #pragma unroll
            for (int nj = 0; nj < 4; nj++) {
                int c0 = n0 + wn0 + nj * 8 + t4 * 2;
                g_cat[(size_t)r * (4 * DMc) + d * DMc + c0]     = acc[mi][nj][half * 2];
                g_cat[(size_t)r * (4 * DMc) + d * DMc + c0 + 1] = acc[mi][nj][half * 2 + 1];
            }
        }
    }
}

// ---------------- 9. final GEMM (double-buffered, SiLU fused on A) ----------------
__global__ void __launch_bounds__(256) k_final(const float* __restrict__ Wf,
                                               float* __restrict__ out) {
    int m0 = blockIdx.x * 128, n0 = blockIdx.y * 64;
    const float* A = g_cat + (size_t)m0 * 1024;
    const float* B = Wf + (size_t)n0 * 1024;
    __shared__ float As[2][16][LDT], Bs[2][16][LDT];
    int tid = threadIdx.x, wid = tid >> 5, lane = tid & 31;
    int wm0 = (wid & 3) * 32, wn0 = (wid >> 2) * 32;
    float acc[2][4][4] = {};
    float4 ra[2], rb;
    fetch128(A, 1024, 0, ra, tid); fetch64(B, 1024, 0, rb, tid);
    store128s(ra, As[0], tid); store64(rb, Bs[0], tid);
    __syncthreads();
    const int NT = 1024 / 16;
    for (int t = 0; t < NT; t++) {
        int cur = t & 1;
        if (t + 1 < NT) {
            fetch128(A, 1024, (t + 1) * 16, ra, tid);
            fetch64 (B, 1024, (t + 1) * 16, rb, tid);
        }
        mma_tile<2,4>(As[cur], Bs[cur], acc, wm0, wn0, lane);
        if (t + 1 < NT) { store128s(ra, As[cur ^ 1], tid); store64(rb, Bs[cur ^ 1], tid); }
        __syncthreads();
    }
    int gid = lane >> 2, t4 = lane & 3;
    #pragma unroll
    for (int mi = 0; mi < 2; mi++) {
        int r0 = m0 + wm0 + mi * 16 + gid, r1 = r0 + 8;
        #pragma unroll
        for (int nj = 0; nj < 4; nj++) {
            int c0 = n0 + wn0 + nj * 8 + t4 * 2;
            out[(size_t)r0 * DMc + c0]     = acc[mi][nj][0];
            out[(size_t)r0 * DMc + c0 + 1] = acc[mi][nj][1];
            out[(size_t)r1 * DMc + c0]     = acc[mi][nj][2];
            out[(size_t)r1 * DMc + c0 + 1] = acc[mi][nj][3];
        }
    }
}

// ---------------- launcher ----------------
extern "C" void kernel_launch(void* const* d_in, const int* in_sizes, int n_in,
                              void* d_out, int out_size) {
    const float* pts      = (const float*)d_in[0];
    const float* in_proj  = (const float*)d_in[2];
    const float* conv_w   = (const float*)d_in[3];
    const float* conv_b   = (const float*)d_in[4];
    const float* dt_bias  = (const float*)d_in[5];
    const float* A_log    = (const float*)d_in[6];
    const float* D_param  = (const float*)d_in[7];
    const float* norm_w   = (const float*)d_in[8];
    const float* outp_w   = (const float*)d_in[9];
    const float* final_w  = (const float*)d_in[10];
    float* out = (float*)d_out;

    k_buildU   <<<dim3(128, 8, 4), dim3(32, 8)>>>(pts);
    k_inproj   <<<dim3(32, 11, 4), 256>>>(in_proj);
    k_conv     <<<dim3(4096, 4),   256>>>(conv_w, conv_b, dt_bias);
    k_scan     <<<dim3(16, 8, 4),  256>>>(A_log);
    k_cb       <<<dim3(2, 2, 64),  256>>>();
    k_states   <<<dim3(1, 1, 512), 256>>>();
    k_chunkscan<<<32, 256>>>();
    k_ssd_y    <<<dim3(2, 1, 512), 256>>>(D_param);
    k_outproj  <<<dim3(32, 2, 4),  256>>>(outp_w, norm_w);
    k_final    <<<dim3(32, 4),     256>>>(final_w, out);
}

// round 17
// speedup vs baseline: 1.1814x; 1.0084x over previous
#include <cuda_runtime.h>
#include <math.h>

// ---------------- problem constants ----------------
#define DMc   256
#define Lc    4096
#define DSc   128
#define DIc   512
#define NHc   8
#define HDc   64
#define CDc   768
#define DIPc  1288
#define CSc   256
#define NCc   16
#define EPSc  1e-5f
#define LDT   136

// ---------------- device scratch ----------------
__device__ float g_U  [4 * Lc * DMc];
__device__ float g_Z  [4 * Lc * DIPc];
__device__ float g_xBC[4 * Lc * CDc];
__device__ float g_dt [4 * Lc * NHc];
__device__ float g_dA [4 * Lc * NHc];
__device__ float g_CB [4 * NCc * CSc * CSc];
__device__ float g_y  [4 * Lc * DIc];
__device__ float g_ssp[4 * Lc * 16];
__device__ float g_st [4 * NCc * NHc * HDc * DSc];
__device__ float g_pv [4 * NCc * NHc * HDc * DSc];
__device__ float g_cat[Lc * 4 * DMc];

__device__ __forceinline__ float silu_f(float x) { return x / (1.f + __expf(-x)); }

// ---------------- tf32 helpers ----------------
__device__ __forceinline__ unsigned f2t(float x) {
    unsigned r; asm("cvt.rna.tf32.f32 %0, %1;" : "=r"(r) : "f"(x)); return r;
}
__device__ __forceinline__ float f2tf(float x) { return __uint_as_float(f2t(x)); }

__device__ __forceinline__ void mma_tf32(float& d0, float& d1, float& d2, float& d3,
                                         unsigned a0, unsigned a1, unsigned a2, unsigned a3,
                                         unsigned b0, unsigned b1) {
    asm volatile("mma.sync.aligned.m16n8k8.row.col.f32.tf32.tf32.f32 "
                 "{%0,%1,%2,%3}, {%4,%5,%6,%7}, {%8,%9}, {%0,%1,%2,%3};\n"
                 : "+f"(d0), "+f"(d1), "+f"(d2), "+f"(d3)
                 : "r"(a0), "r"(a1), "r"(a2), "r"(a3), "r"(b0), "r"(b1));
}

template<int MF, int NF>
__device__ __forceinline__ void mma_tile(const float (*As)[LDT], const float (*Bs)[LDT],
                                         float acc[MF][NF][4], int wm0, int wn0, int lane) {
    int gid = lane >> 2, t4 = lane & 3;
    #pragma unroll
    for (int ks = 0; ks < 16; ks += 8) {
        unsigned a[MF][4], b[NF][2];
        #pragma unroll
        for (int mi = 0; mi < MF; mi++) {
            int m = wm0 + mi * 16 + gid;
            a[mi][0] = __float_as_uint(As[ks + t4    ][m]);
            a[mi][1] = __float_as_uint(As[ks + t4    ][m + 8]);
            a[mi][2] = __float_as_uint(As[ks + t4 + 4][m]);
            a[mi][3] = __float_as_uint(As[ks + t4 + 4][m + 8]);
        }
        #pragma unroll
        for (int nj = 0; nj < NF; nj++) {
            int n = wn0 + nj * 8 + gid;
            b[nj][0] = __float_as_uint(Bs[ks + t4    ][n]);
            b[nj][1] = __float_as_uint(Bs[ks + t4 + 4][n]);
        }
        #pragma unroll
        for (int mi = 0; mi < MF; mi++)
            #pragma unroll
            for (int nj = 0; nj < NF; nj++)
                mma_tf32(acc[mi][nj][0], acc[mi][nj][1], acc[mi][nj][2], acc[mi][nj][3],
                         a[mi][0], a[mi][1], a[mi][2], a[mi][3], b[nj][0], b[nj][1]);
    }
}

// ======== register-staged fetch / smem store (BK=16) ========
__device__ __forceinline__ void fetch128(const float* __restrict__ G, int ld, int k0,
                                         float4 r[2], int tid) {
    #pragma unroll
    for (int h = 0; h < 2; h++) {
        int e = tid * 4 + h * 1024; int kk = e & 15; int rr = e >> 4;
        r[h] = *(const float4*)(G + (size_t)rr * ld + k0 + kk);
    }
}
__device__ __forceinline__ void fetch128m(const float* __restrict__ G, int ld, int k0, int rlim,
                                          float4 r[2], int tid) {
    #pragma unroll
    for (int h = 0; h < 2; h++) {
        int e = tid * 4 + h * 1024; int kk = e & 15; int rr = e >> 4;
        r[h] = make_float4(0.f, 0.f, 0.f, 0.f);
        if (rr < rlim) r[h] = *(const float4*)(G + (size_t)rr * ld + k0 + kk);
    }
}
__device__ __forceinline__ void store128(const float4 r[2], float (*S)[LDT], int tid) {
    #pragma unroll
    for (int h = 0; h < 2; h++) {
        int e = tid * 4 + h * 1024; int kk = e & 15; int rr = e >> 4;
        S[kk][rr] = f2tf(r[h].x); S[kk+1][rr] = f2tf(r[h].y);
        S[kk+2][rr] = f2tf(r[h].z); S[kk+3][rr] = f2tf(r[h].w);
    }
}
__device__ __forceinline__ void store128s(const float4 r[2], float (*S)[LDT], int tid) {
    #pragma unroll
    for (int h = 0; h < 2; h++) {
        int e = tid * 4 + h * 1024; int kk = e & 15; int rr = e >> 4;
        S[kk][rr] = f2tf(silu_f(r[h].x)); S[kk+1][rr] = f2tf(silu_f(r[h].y));
        S[kk+2][rr] = f2tf(silu_f(r[h].z)); S[kk+3][rr] = f2tf(silu_f(r[h].w));
    }
}
__device__ __forceinline__ void store128n(const float4 r[2], float (*S)[LDT], int tid,
                                          const float* rs, const float* nw, int k0) {
    #pragma unroll
    for (int h = 0; h < 2; h++) {
        int e = tid * 4 + h * 1024; int kk = e & 15; int rr = e >> 4;
        float sc = rs[rr];
        S[kk][rr]   = f2tf(r[h].x * sc * nw[k0 + kk]);
        S[kk+1][rr] = f2tf(r[h].y * sc * nw[k0 + kk + 1]);
        S[kk+2][rr] = f2tf(r[h].z * sc * nw[k0 + kk + 2]);
        S[kk+3][rr] = f2tf(r[h].w * sc * nw[k0 + kk + 3]);
    }
}
__device__ __forceinline__ void fetch64(const float* __restrict__ G, int ld, int k0,
                                        float4& r, int tid) {
    int e = tid * 4; int kk = e & 15; int rr = e >> 4;
    r = *(const float4*)(G + (size_t)rr * ld + k0 + kk);
}
__device__ __forceinline__ void store64(const float4 r, float (*S)[LDT], int tid) {
    int e = tid * 4; int kk = e & 15; int rr = e >> 4;
    S[kk][rr] = f2tf(r.x); S[kk+1][rr] = f2tf(r.y);
    S[kk+2][rr] = f2tf(r.z); S[kk+3][rr] = f2tf(r.w);
}

// ---------------- 0. gather + transpose ----------------
__global__ void k_buildU(const float* __restrict__ pts) {
    int d  = blockIdx.z;
    int lt = blockIdx.x * 32;
    int mt = blockIdx.y * 32;
    __shared__ float tile[32][33];
    int tx = threadIdx.x, ty = threadIdx.y;
    #pragma unroll
    for (int r = 0; r < 4; r++) {
        int i = ty + r * 8;
        int l = lt + tx;
        int lp;
        if      (d == 0) lp = l;
        else if (d == 1) lp = 4095 - l;
        else if (d == 2) lp = (l & 63) * 64 + (l >> 6);
        else             { int lv = 4095 - l; lp = (lv & 63) * 64 + (lv >> 6); }
        tile[i][tx] = pts[(mt + i) * Lc + lp];
    }
    __syncthreads();
    #pragma unroll
    for (int r = 0; r < 4; r++) {
        int i = ty + r * 8;
        g_U[(size_t)(d * Lc + lt + i) * DMc + mt + tx] = tile[tx][i];
    }
}

// ---------------- 1. in-proj (double-buffered) ----------------
__global__ void __launch_bounds__(256) k_inproj(const float* __restrict__ Win) {
    int d = blockIdx.z;
    int m0 = blockIdx.x * 128, n0 = blockIdx.y * 128;
    const float* A = g_U + (size_t)d * Lc * DMc + (size_t)m0 * DMc;
    const float* B = Win + (size_t)d * DIPc * DMc + (size_t)n0 * DMc;
    int nrem = DIPc - n0;
    __shared__ float As[2][16][LDT], Bs[2][16][LDT];
    int tid = threadIdx.x, wid = tid >> 5, lane = tid & 31;
    int wm0 = (wid & 1) * 64, wn0 = (wid >> 1) * 32;
    float acc[4][4][4] = {};
    float4 ra[2], rb[2];
    fetch128 (A, DMc, 0, ra, tid);
    fetch128m(B, DMc, 0, nrem, rb, tid);
    store128(ra, As[0], tid); store128(rb, Bs[0], tid);
    __syncthreads();
    const int NT = DMc / 16;
    for (int t = 0; t < NT; t++) {
        int cur = t & 1;
        if (t + 1 < NT) {
            fetch128 (A, DMc, (t + 1) * 16, ra, tid);
            fetch128m(B, DMc, (t + 1) * 16, nrem, rb, tid);
        }
        mma_tile<4,4>(As[cur], Bs[cur], acc, wm0, wn0, lane);
        if (t + 1 < NT) { store128(ra, As[cur ^ 1], tid); store128(rb, Bs[cur ^ 1], tid); }
        __syncthreads();
    }
    int gid = lane >> 2, t4 = lane & 3;
    #pragma unroll
    for (int mi = 0; mi < 4; mi++) {
        int r0 = m0 + wm0 + mi * 16 + gid, r1 = r0 + 8;
        #pragma unroll
        for (int nj = 0; nj < 4; nj++) {
            int c0 = n0 + wn0 + nj * 8 + t4 * 2;
            if (c0 < DIPc) {
                g_Z[(size_t)(d * Lc + r0) * DIPc + c0]     = acc[mi][nj][0];
                g_Z[(size_t)(d * Lc + r0) * DIPc + c0 + 1] = acc[mi][nj][1];
                g_Z[(size_t)(d * Lc + r1) * DIPc + c0]     = acc[mi][nj][2];
                g_Z[(size_t)(d * Lc + r1) * DIPc + c0 + 1] = acc[mi][nj][3];
            }
        }
    }
}

// ---------------- 2. conv1d + silu ; softplus dt ----------------
__global__ void __launch_bounds__(256) k_conv(const float* __restrict__ conv_w,
                                              const float* __restrict__ conv_b,
                                              const float* __restrict__ dt_bias) {
    int l = blockIdx.x, d = blockIdx.y, tid = threadIdx.x;
    for (int ch = tid; ch < CDc; ch += 256) {
        float acc = conv_b[d * CDc + ch];
        const float* cw = conv_w + (size_t)(d * CDc + ch) * 4;
        #pragma unroll
        for (int w = 0; w < 4; w++) {
            int ls = l - 3 + w;
            if (ls >= 0)
                acc += g_Z[(size_t)(d * Lc + ls) * DIPc + DIc + ch] * cw[w];
        }
        g_xBC[(size_t)(d * Lc + l) * CDc + ch] = silu_f(acc);
    }
    if (tid < NHc) {
        float v = g_Z[(size_t)(d * Lc + l) * DIPc + (DIc + CDc) + tid] + dt_bias[d * NHc + tid];
        float sp = (v > 20.f) ? v : log1pf(__expf(v));
        g_dt[(size_t)(d * Lc + l) * NHc + tid] = sp;
    }
}

// ---------------- 3. per-chunk cumsum of dt*A ----------------
__global__ void __launch_bounds__(256) k_scan(const float* __restrict__ A_log) {
    int c = blockIdx.x, h = blockIdx.y, d = blockIdx.z, s = threadIdx.x;
    float A = -__expf(A_log[d * NHc + h]);
    __shared__ float buf[256];
    buf[s] = g_dt[(size_t)(d * Lc + c * CSc + s) * NHc + h] * A;
    __syncthreads();
    for (int off = 1; off < 256; off <<= 1) {
        float t = (s >= off) ? buf[s - off] : 0.f;
        __syncthreads();
        buf[s] += t;
        __syncthreads();
    }
    g_dA[(size_t)(d * Lc + c * CSc + s) * NHc + h] = buf[s];
}

// ---------------- 4. CB = C @ B^T (double-buffered) ----------------
__global__ void __launch_bounds__(256) k_cb() {
    int dc = blockIdx.z; int d = dc >> 4, c = dc & 15;
    int i0 = blockIdx.x * 128, j0 = blockIdx.y * 128;
    const float* base = g_xBC + (size_t)(d * Lc + c * CSc) * CDc;
    const float* A = base + (size_t)i0 * CDc + (DIc + DSc);
    const float* B = base + (size_t)j0 * CDc + DIc;
    __shared__ float As[2][16][LDT], Bs[2][16][LDT];
    int tid = threadIdx.x, wid = tid >> 5, lane = tid & 31;
    int wm0 = (wid & 1) * 64, wn0 = (wid >> 1) * 32;
    float acc[4][4][4] = {};
    float4 ra[2], rb[2];
    fetch128(A, CDc, 0, ra, tid); fetch128(B, CDc, 0, rb, tid);
    store128(ra, As[0], tid); store128(rb, Bs[0], tid);
    __syncthreads();
    const int NT = DSc / 16;
    for (int t = 0; t < NT; t++) {
        int cur = t & 1;
        if (t + 1 < NT) {
            fetch128(A, CDc, (t + 1) * 16, ra, tid);
            fetch128(B, CDc, (t + 1) * 16, rb, tid);
        }
        mma_tile<4,4>(As[cur], Bs[cur], acc, wm0, wn0, lane);
        if (t + 1 < NT) { store128(ra, As[cur ^ 1], tid); store128(rb, Bs[cur ^ 1], tid); }
        __syncthreads();
    }
    float* out = g_CB + (size_t)(d * NCc + c) * CSc * CSc;
    int gid = lane >> 2, t4 = lane & 3;
    #pragma unroll
    for (int mi = 0; mi < 4; mi++) {
        int r0 = i0 + wm0 + mi * 16 + gid, r1 = r0 + 8;
        #pragma unroll
        for (int nj = 0; nj < 4; nj++) {
            int c0 = j0 + wn0 + nj * 8 + t4 * 2;
            out[r0 * CSc + c0]     = acc[mi][nj][0];
            out[r0 * CSc + c0 + 1] = acc[mi][nj][1];
            out[r1 * CSc + c0]     = acc[mi][nj][2];
            out[r1 * CSc + c0 + 1] = acc[mi][nj][3];
        }
    }
}

// ---------------- 5. states[p][n] (double-buffered) ----------------
__global__ void __launch_bounds__(256) k_states() {
    int z = blockIdx.z; int d = z >> 7, c = (z >> 3) & 15, h = z & 7;
    __shared__ float Aw[2][16][LDT], Bsh[2][16][LDT];
    __shared__ float daF[256], dtF[256];
    int tid = threadIdx.x, wid = tid >> 5, lane = tid & 31;
    int wm0 = (wid & 1) * 32, wn0 = (wid >> 1) * 32;
    daF[tid] = g_dA[(size_t)(d * Lc + c * CSc + tid) * NHc + h];
    dtF[tid] = g_dt[(size_t)(d * Lc + c * CSc + tid) * NHc + h];
    __syncthreads();
    float daL = daF[255];
    const float* base = g_xBC + (size_t)(d * Lc + c * CSc) * CDc;
    const float* Abase = base + h * HDc;       // X[s][p], ld=CDc (64 wide)
    const float* Bbase = base + DIc;           // B[s][n], ld=CDc (128 wide)
    int eA = tid * 4; int colA = eA & 63; int ssA = eA >> 6;   // per-thread A-slot
    float acc[2][4][4] = {};
    float4 rA; float4 rB[2];
    // prefetch tile 0 (rows = s-index)
    rA = *(const float4*)(Abase + (size_t)(0 + ssA) * CDc + colA);
    #pragma unroll
    for (int hh = 0; hh < 2; hh++) {
        int e = tid * 4 + hh * 1024; int col = e & 127; int ss = e >> 7;
        rB[hh] = *(const float4*)(Bbase + (size_t)(0 + ss) * CDc + col);
    }
    {   // store tile 0
        float w = dtF[ssA] * __expf(daL - daF[ssA]);
        Aw[0][ssA][colA] = f2tf(rA.x*w); Aw[0][ssA][colA+1] = f2tf(rA.y*w);
        Aw[0][ssA][colA+2] = f2tf(rA.z*w); Aw[0][ssA][colA+3] = f2tf(rA.w*w);
        #pragma unroll
        for (int hh = 0; hh < 2; hh++) {
            int e = tid * 4 + hh * 1024; int col = e & 127; int ss = e >> 7;
            Bsh[0][ss][col] = f2tf(rB[hh].x); Bsh[0][ss][col+1] = f2tf(rB[hh].y);
            Bsh[0][ss][col+2] = f2tf(rB[hh].z); Bsh[0][ss][col+3] = f2tf(rB[hh].w);
        }
    }
    __syncthreads();
    const int NT = CSc / 16;   // 16 tiles of s
    for (int t = 0; t < NT; t++) {
        int cur = t & 1;
        int s1 = (t + 1) * 16;
        if (t + 1 < NT) {
            rA = *(const float4*)(Abase + (size_t)(s1 + ssA) * CDc + colA);
            #pragma unroll
            for (int hh = 0; hh < 2; hh++) {
                int e = tid * 4 + hh * 1024; int col = e & 127; int ss = e >> 7;
                rB[hh] = *(const float4*)(Bbase + (size_t)(s1 + ss) * CDc + col);
            }
        }
        mma_tile<2,4>(Aw[cur], Bsh[cur], acc, wm0, wn0, lane);
        if (t + 1 < NT) {
            int nb = cur ^ 1;
            float w = dtF[s1 + ssA] * __expf(daL - daF[s1 + ssA]);
            Aw[nb][ssA][colA] = f2tf(rA.x*w); Aw[nb][ssA][colA+1] = f2tf(rA.y*w);
            Aw[nb][ssA][colA+2] = f2tf(rA.z*w); Aw[nb][ssA][colA+3] = f2tf(rA.w*w);
            #pragma unroll
            for (int hh = 0; hh < 2; hh++) {
                int e = tid * 4 + hh * 1024; int col = e & 127; int ss = e >> 7;
                Bsh[nb][ss][col] = f2tf(rB[hh].x); Bsh[nb][ss][col+1] = f2tf(rB[hh].y);
                Bsh[nb][ss][col+2] = f2tf(rB[hh].z); Bsh[nb][ss][col+3] = f2tf(rB[hh].w);
            }
        }
        __syncthreads();
    }
    float* out = g_st + (size_t)((d * NCc + c) * NHc + h) * HDc * DSc;
    int gid = lane >> 2, t4 = lane & 3;
    #pragma unroll
    for (int mi = 0; mi < 2; mi++) {
        int r0 = wm0 + mi * 16 + gid, r1 = r0 + 8;
        #pragma unroll
        for (int nj = 0; nj < 4; nj++) {
            int c0 = wn0 + nj * 8 + t4 * 2;
            out[r0 * DSc + c0]     = acc[mi][nj][0];
            out[r0 * DSc + c0 + 1] = acc[mi][nj][1];
            out[r1 * DSc + c0]     = acc[mi][nj][2];
            out[r1 * DSc + c0 + 1] = acc[mi][nj][3];
        }
    }
}

// ---------------- 6. inter-chunk scan ----------------
__global__ void __launch_bounds__(256) k_chunkscan() {
    int dh = blockIdx.x; int d = dh >> 3, h = dh & 7;
    int tid = threadIdx.x;
    float carry[32];
    #pragma unroll
    for (int t = 0; t < 32; t++) carry[t] = 0.f;
    for (int c = 0; c < NCc; c++) {
        float cd = __expf(g_dA[(size_t)(d * Lc + c * CSc + 255) * NHc + h]);
        size_t off = (size_t)((d * NCc + c) * NHc + h) * 8192;
        #pragma unroll
        for (int t = 0; t < 32; t++) {
            int e = tid + t * 256;
            g_pv[off + e] = carry[t];
            carry[t] = carry[t] * cd + g_st[off + e];
        }
    }
}

// ---------------- 7. SSD y (double-buffered) + gate + partial sumsq ----------------
__global__ void __launch_bounds__(256) k_ssd_y(const float* __restrict__ D_param) {
    int i0 = blockIdx.x * 128;
    int z  = blockIdx.z; int d = z >> 7, c = (z >> 3) & 15, h = z & 7;
    __shared__ float Ss[2][16][LDT], Xs[2][16][LDT];
    __shared__ float daF[256], dtF[256], eI[128];
    int tid = threadIdx.x, wid = tid >> 5, lane = tid & 31;
    int wm0 = (wid & 3) * 32, wn0 = (wid >> 2) * 32;
    daF[tid] = g_dA[(size_t)(d * Lc + c * CSc + tid) * NHc + h];
    dtF[tid] = g_dt[(size_t)(d * Lc + c * CSc + tid) * NHc + h];
    __syncthreads();
    if (tid < 128) eI[tid] = __expf(daF[i0 + tid]);
    __syncthreads();
    const float* cbb   = g_CB + (size_t)(d * NCc + c) * CSc * CSc;
    const float* base  = g_xBC + (size_t)(d * Lc + c * CSc) * CDc;
    const float* xbase = base + h * HDc;
    float acc[2][4][4] = {};
    float4 rcb[2], rx;
    int eX = tid * 4; int pX = eX & 63; int jjX = eX >> 6;
    // ---- phase 1: diag (16 j-tiles, double-buffered) ----
    #pragma unroll
    for (int hh = 0; hh < 2; hh++) {
        int e = tid * 4 + hh * 1024; int kk = e & 15; int ii = e >> 4;
        rcb[hh] = *(const float4*)(cbb + (i0 + ii) * CSc + 0 + kk);
    }
    rx = *(const float4*)(xbase + (size_t)(0 + jjX) * CDc + pX);
    {   // store tile 0
        #pragma unroll
        for (int hh = 0; hh < 2; hh++) {
            int e = tid * 4 + hh * 1024; int kk = e & 15; int ii = e >> 4;
            float r[4] = {rcb[hh].x, rcb[hh].y, rcb[hh].z, rcb[hh].w};
            float dai = daF[i0 + ii]; int ig = i0 + ii;
            #pragma unroll
            for (int q = 0; q < 4; q++) {
                int jg = 0 + kk + q;
                float sv = 0.f;
                if (jg <= ig) sv = r[q] * __expf(dai - daF[jg]) * dtF[jg];
                Ss[0][kk + q][ii] = f2tf(sv);
            }
        }
        Xs[0][jjX][pX] = f2tf(rx.x); Xs[0][jjX][pX+1] = f2tf(rx.y);
        Xs[0][jjX][pX+2] = f2tf(rx.z); Xs[0][jjX][pX+3] = f2tf(rx.w);
    }
    __syncthreads();
    for (int t = 0; t < 16; t++) {
        int cur = t & 1;
        int j1 = (t + 1) * 16;
        if (t + 1 < 16) {
            #pragma unroll
            for (int hh = 0; hh < 2; hh++) {
                int e = tid * 4 + hh * 1024; int kk = e & 15; int ii = e >> 4;
                rcb[hh] = *(const float4*)(cbb + (i0 + ii) * CSc + j1 + kk);
            }
            rx = *(const float4*)(xbase + (size_t)(j1 + jjX) * CDc + pX);
        }
        mma_tile<2,4>(Ss[cur], Xs[cur], acc, wm0, wn0, lane);
        if (t + 1 < 16) {
            int nb = cur ^ 1;
            #pragma unroll
            for (int hh = 0; hh < 2; hh++) {
                int e = tid * 4 + hh * 1024; int kk = e & 15; int ii = e >> 4;
                float r[4] = {rcb[hh].x, rcb[hh].y, rcb[hh].z, rcb[hh].w};
                float dai = daF[i0 + ii]; int ig = i0 + ii;
                #pragma unroll
                for (int q = 0; q < 4; q++) {
                    int jg = j1 + kk + q;
                    float sv = 0.f;
                    if (jg <= ig) sv = r[q] * __expf(dai - daF[jg]) * dtF[jg];
                    Ss[nb][kk + q][ii] = f2tf(sv);
                }
            }
            Xs[nb][jjX][pX] = f2tf(rx.x); Xs[nb][jjX][pX+1] = f2tf(rx.y);
            Xs[nb][jjX][pX+2] = f2tf(rx.z); Xs[nb][jjX][pX+3] = f2tf(rx.w);
        }
        __syncthreads();
    }
    // ---- phase 2: off-diag (8 k-tiles, double-buffered), exp(dAi) folded into C ----
    const float* Cb = base + (size_t)i0 * CDc + (DIc + DSc);
    const float* pv = g_pv + (size_t)((d * NCc + c) * NHc + h) * HDc * DSc;
    float4 rc[2], rpv;
    int eP = tid * 4; int kkP = eP & 15; int rrP = eP >> 4;
    #pragma unroll
    for (int hh = 0; hh < 2; hh++) {
        int e = tid * 4 + hh * 1024; int kk = e & 15; int ii = e >> 4;
        rc[hh] = *(const float4*)(Cb + (size_t)ii * CDc + 0 + kk);
    }
    rpv = *(const float4*)(pv + (size_t)rrP * DSc + 0 + kkP);
    {
        #pragma unroll
        for (int hh = 0; hh < 2; hh++) {
            int e = tid * 4 + hh * 1024; int kk = e & 15; int ii = e >> 4;
            float ei = eI[ii];
            Ss[0][kk][ii]   = f2tf(rc[hh].x * ei); Ss[0][kk+1][ii] = f2tf(rc[hh].y * ei);
            Ss[0][kk+2][ii] = f2tf(rc[hh].z * ei); Ss[0][kk+3][ii] = f2tf(rc[hh].w * ei);
        }
        Xs[0][kkP][rrP] = f2tf(rpv.x); Xs[0][kkP+1][rrP] = f2tf(rpv.y);
        Xs[0][kkP+2][rrP] = f2tf(rpv.z); Xs[0][kkP+3][rrP] = f2tf(rpv.w);
    }
    __syncthreads();
    for (int t = 0; t < 8; t++) {
        int cur = t & 1;
        int k1 = (t + 1) * 16;
        if (t + 1 < 8) {
            #pragma unroll
            for (int hh = 0; hh < 2; hh++) {
                int e = tid * 4 + hh * 1024; int kk = e & 15; int ii = e >> 4;
                rc[hh] = *(const float4*)(Cb + (size_t)ii * CDc + k1 + kk);
            }
            rpv = *(const float4*)(pv + (size_t)rrP * DSc + k1 + kkP);
        }
        mma_tile<2,4>(Ss[cur], Xs[cur], acc, wm0, wn0, lane);
        if (t + 1 < 8) {
            int nb = cur ^ 1;
            #pragma unroll
            for (int hh = 0; hh < 2; hh++) {
                int e = tid * 4 + hh * 1024; int kk = e & 15; int ii = e >> 4;
                float ei = eI[ii];
                Ss[nb][kk][ii]   = f2tf(rc[hh].x * ei); Ss[nb][kk+1][ii] = f2tf(rc[hh].y * ei);
                Ss[nb][kk+2][ii] = f2tf(rc[hh].z * ei); Ss[nb][kk+3][ii] = f2tf(rc[hh].w * ei);
            }
            Xs[nb][kkP][rrP] = f2tf(rpv.x); Xs[nb][kkP+1][rrP] = f2tf(rpv.y);
            Xs[nb][kkP+2][rrP] = f2tf(rpv.z); Xs[nb][kkP+3][rrP] = f2tf(rpv.w);
        }
        __syncthreads();
    }
    float Dh = D_param[d * NHc + h];
    int gid = lane >> 2, t4 = lane & 3;
    int half = wn0 >> 5;
    #pragma unroll
    for (int mi = 0; mi < 2; mi++) {
        int lr0 = wm0 + mi * 16 + gid, lr1 = lr0 + 8;
        int l0 = c * CSc + i0 + lr0, l1 = c * CSc + i0 + lr1;
        float s0 = 0.f, s1 = 0.f;
        #pragma unroll
        for (int nj = 0; nj < 4; nj++) {
            int p0 = wn0 + nj * 8 + t4 * 2;
            size_t y0 = (size_t)(d * Lc + l0) * DIc + h * HDc + p0;
            size_t y1 = (size_t)(d * Lc + l1) * DIc + h * HDc + p0;
            size_t x0 = (size_t)(d * Lc + l0) * CDc + h * HDc + p0;
            size_t x1 = (size_t)(d * Lc + l1) * CDc + h * HDc + p0;
            size_t z0 = (size_t)(d * Lc + l0) * DIPc + h * HDc + p0;
            size_t z1 = (size_t)(d * Lc + l1) * DIPc + h * HDc + p0;
            float v00 = (acc[mi][nj][0] + Dh * g_xBC[x0])     * silu_f(g_Z[z0]);
            float v01 = (acc[mi][nj][1] + Dh * g_xBC[x0 + 1]) * silu_f(g_Z[z0 + 1]);
            float v10 = (acc[mi][nj][2] + Dh * g_xBC[x1])     * silu_f(g_Z[z1]);
            float v11 = (acc[mi][nj][3] + Dh * g_xBC[x1 + 1]) * silu_f(g_Z[z1 + 1]);
            g_y[y0] = v00; g_y[y0 + 1] = v01;
            g_y[y1] = v10; g_y[y1 + 1] = v11;
            s0 += v00 * v00 + v01 * v01;
            s1 += v10 * v10 + v11 * v11;
        }
        s0 += __shfl_xor_sync(0xffffffffu, s0, 1);
        s0 += __shfl_xor_sync(0xffffffffu, s0, 2);
        s1 += __shfl_xor_sync(0xffffffffu, s1, 1);
        s1 += __shfl_xor_sync(0xffffffffu, s1, 2);
        if (t4 == 0) {
            g_ssp[(size_t)(d * Lc + l0) * 16 + h * 2 + half] = s0;
            g_ssp[(size_t)(d * Lc + l1) * 16 + h * 2 + half] = s1;
        }
    }
}

// ---------------- 8. out-proj (fused RMSNorm on A) + permuted scatter ----------------
__global__ void __launch_bounds__(256) k_outproj(const float* __restrict__ Wout,
                                                 const float* __restrict__ norm_w) {
    int d = blockIdx.z;
    int m0 = blockIdx.x * 128, n0 = blockIdx.y * 128;
    const float* A = g_y + (size_t)d * Lc * DIc + (size_t)m0 * DIc;
    const float* B = Wout + (size_t)d * DMc * DIc + (size_t)n0 * DIc;
    __shared__ float As[2][16][LDT], Bs[2][16][LDT];
    __shared__ float rs[128], nwsm[DIc];
    int tid = threadIdx.x, wid = tid >> 5, lane = tid & 31;
    int wm0 = (wid & 1) * 64, wn0 = (wid >> 1) * 32;
    #pragma unroll
    for (int i = tid; i < DIc; i += 256) nwsm[i] = norm_w[d * DIc + i];
    if (tid < 128) {
        const float* pp = g_ssp + (size_t)(d * Lc + m0 + tid) * 16;
        float s = 0.f;
        #pragma unroll
        for (int i = 0; i < 16; i++) s += pp[i];
        rs[tid] = rsqrtf(s / (float)DIc + EPSc);
    }
    __syncthreads();
    float acc[4][4][4] = {};
    float4 ra[2], rb[2];
    fetch128(A, DIc, 0, ra, tid); fetch128(B, DIc, 0, rb, tid);
    store128n(ra, As[0], tid, rs, nwsm, 0); store128(rb, Bs[0], tid);
    __syncthreads();
    const int NT = DIc / 16;
    for (int t = 0; t < NT; t++) {
        int cur = t & 1;
        if (t + 1 < NT) {
            fetch128(A, DIc, (t + 1) * 16, ra, tid);
            fetch128(B, DIc, (t + 1) * 16, rb, tid);
        }
        mma_tile<4,4>(As[cur], Bs[cur], acc, wm0, wn0, lane);
        if (t + 1 < NT) {
            store128n(ra, As[cur ^ 1], tid, rs, nwsm, (t + 1) * 16);
            store128(rb, Bs[cur ^ 1], tid);
        }
        __syncthreads();
    }
    int gid = lane >> 2, t4 = lane & 3;
    #pragma unroll
    for (int mi = 0; mi < 4; mi++) {
        #pragma unroll
        for (int half = 0; half < 2; half++) {
            int l = m0 + wm0 + mi * 16 + gid + half * 8;
            int r;
            if      (d == 0) r = l;
            else if (d == 1) r = 4095 - l;
            else if (d == 2) r = (l & 63) * 64 + (l >> 6);
            else             { int lv = 4095 - l; r = (lv & 63) * 64 + (lv >> 6); }
            #pragma unroll
            for (int nj = 0; nj < 4; nj++) {
                int c0 = n0 + wn0 + nj * 8 + t4 * 2;
                g_cat[(size_t)r * (4 * DMc) + d * DMc + c0]     = acc[mi][nj][half * 2];
                g_cat[(size_t)r * (4 * DMc) + d * DMc + c0 + 1] = acc[mi][nj][half * 2 + 1];
            }
        }
    }
}

// ---------------- 9. final GEMM (double-buffered, SiLU fused on A) ----------------
__global__ void __launch_bounds__(256) k_final(const float* __restrict__ Wf,
                                               float* __restrict__ out) {
    int m0 = blockIdx.x * 128, n0 = blockIdx.y * 64;
    const float* A = g_cat + (size_t)m0 * 1024;
    const float* B = Wf + (size_t)n0 * 1024;
    __shared__ float As[2][16][LDT], Bs[2][16][LDT];
    int tid = threadIdx.x, wid = tid >> 5, lane = tid & 31;
    int wm0 = (wid & 3) * 32, wn0 = (wid >> 2) * 32;
    float acc[2][4][4] = {};
    float4 ra[2], rb;
    fetch128(A, 1024, 0, ra, tid); fetch64(B, 1024, 0, rb, tid);
    store128s(ra, As[0], tid); store64(rb, Bs[0], tid);
    __syncthreads();
    const int NT = 1024 / 16;
    for (int t = 0; t < NT; t++) {
        int cur = t & 1;
        if (t + 1 < NT) {
            fetch128(A, 1024, (t + 1) * 16, ra, tid);
            fetch64 (B, 1024, (t + 1) * 16, rb, tid);
        }
        mma_tile<2,4>(As[cur], Bs[cur], acc, wm0, wn0, lane);
        if (t + 1 < NT) { store128s(ra, As[cur ^ 1], tid); store64(rb, Bs[cur ^ 1], tid); }
        __syncthreads();
    }
    int gid = lane >> 2, t4 = lane & 3;
    #pragma unroll
    for (int mi = 0; mi < 2; mi++) {
        int r0 = m0 + wm0 + mi * 16 + gid, r1 = r0 + 8;
        #pragma unroll
        for (int nj = 0; nj < 4; nj++) {
            int c0 = n0 + wn0 + nj * 8 + t4 * 2;
            out[(size_t)r0 * DMc + c0]     = acc[mi][nj][0];
            out[(size_t)r0 * DMc + c0 + 1] = acc[mi][nj][1];
            out[(size_t)r1 * DMc + c0]     = acc[mi][nj][2];
            out[(size_t)r1 * DMc + c0 + 1] = acc[mi][nj][3];
        }
    }
}

// ---------------- launcher ----------------
extern "C" void kernel_launch(void* const* d_in, const int* in_sizes, int n_in,
                              void* d_out, int out_size) {
    const float* pts      = (const float*)d_in[0];
    const float* in_proj  = (const float*)d_in[2];
    const float* conv_w   = (const float*)d_in[3];
    const float* conv_b   = (const float*)d_in[4];
    const float* dt_bias  = (const float*)d_in[5];
    const float* A_log    = (const float*)d_in[6];
    const float* D_param  = (const float*)d_in[7];
    const float* norm_w   = (const float*)d_in[8];
    const float* outp_w   = (const float*)d_in[9];
    const float* final_w  = (const float*)d_in[10];
    float* out = (float*)d_out;

    k_buildU   <<<dim3(128, 8, 4), dim3(32, 8)>>>(pts);
    k_inproj   <<<dim3(32, 11, 4), 256>>>(in_proj);
    k_conv     <<<dim3(4096, 4),   256>>>(conv_w, conv_b, dt_bias);
    k_scan     <<<dim3(16, 8, 4),  256>>>(A_log);
    k_cb       <<<dim3(2, 2, 64),  256>>>();
    k_states   <<<dim3(1, 1, 512), 256>>>();
    k_chunkscan<<<32, 256>>>();
    k_ssd_y    <<<dim3(2, 1, 512), 256>>>(D_param);
    k_outproj  <<<dim3(32, 2, 4),  256>>>(outp_w, norm_w);
    k_final    <<<dim3(32, 4),     256>>>(final_w, out);
}